// round 2
// baseline (speedup 1.0000x reference)
#include <cuda_runtime.h>
#include <cuda_bf16.h>

// Problem: elementwise theta-step + scalar residual-norm reduction.
// x: (4096, 16384) fp32 -> out: same shape, plus fmin scalar appended.
// Single persistent kernel: last-block-done pattern folds the final
// reduction into the main kernel (removes the 8us reduce_kernel tail).

#define NBLOCKS   3552      // 148 SMs * 24 blocks
#define NTHREADS  256
#define NWARPS    (NTHREADS / 32)

__device__ float        g_partials[NBLOCKS];
__device__ unsigned int g_ticket = 0;

__device__ __forceinline__ float proc_one(float x, float& r2acc) {
    // explicit = x + 0.5*relu(x)
    float e = fmaf(0.5f, fmaxf(x, 0.0f), x);
    float z = e;
    #pragma unroll
    for (int k = 0; k < 10; ++k) {
        z = fmaf(0.5f, fmaxf(z, 0.0f), e);
    }
    float rz = fmaxf(z, 0.0f);
    float o  = fmaf(0.5f, rz, e);
    // residual in reference order: (z - explicit) - 0.5*relu(z)
    float r  = (z - e) - 0.5f * rz;
    r2acc = fmaf(r, r, r2acc);
    return o;
}

__global__ void __launch_bounds__(NTHREADS)
step_kernel(const float4* __restrict__ x4, float4* __restrict__ out4,
            int n4, float* __restrict__ out_scalar) {
    int tid    = blockIdx.x * NTHREADS + threadIdx.x;
    int stride = gridDim.x * NTHREADS;

    float local = 0.0f;
    for (int i = tid; i < n4; i += stride) {
        float4 v = __ldcs(&x4[i]);           // evict-first: no L2 reuse
        float4 o;
        o.x = proc_one(v.x, local);
        o.y = proc_one(v.y, local);
        o.z = proc_one(v.z, local);
        o.w = proc_one(v.w, local);
        __stcs(&out4[i], o);                 // streaming store
    }

    // ---- block reduction of r^2 partial (fp32) ----
    #pragma unroll
    for (int off = 16; off > 0; off >>= 1)
        local += __shfl_down_sync(0xffffffffu, local, off);

    __shared__ float warpsum[NWARPS];
    int lane = threadIdx.x & 31;
    int wid  = threadIdx.x >> 5;
    if (lane == 0) warpsum[wid] = local;
    __syncthreads();

    __shared__ bool s_is_last;
    if (threadIdx.x == 0) {
        float v = 0.0f;
        #pragma unroll
        for (int w = 0; w < NWARPS; ++w) v += warpsum[w];
        g_partials[blockIdx.x] = v;
        __threadfence();                      // partial visible before ticket
        unsigned int t = atomicAdd(&g_ticket, 1u);
        s_is_last = (t == (unsigned int)(gridDim.x - 1));
        if (s_is_last) g_ticket = 0;          // reset for graph replay
    }
    __syncthreads();

    // ---- last block: final reduction over all partials (double) ----
    if (s_is_last) {
        double acc = 0.0;
        for (int i = threadIdx.x; i < NBLOCKS; i += NTHREADS)
            acc += (double)g_partials[i];

        #pragma unroll
        for (int off = 16; off > 0; off >>= 1)
            acc += __shfl_down_sync(0xffffffffu, acc, off);

        __shared__ double dsum[NWARPS];
        if (lane == 0) dsum[wid] = acc;
        __syncthreads();

        if (threadIdx.x == 0) {
            double v = 0.0;
            #pragma unroll
            for (int w = 0; w < NWARPS; ++w) v += dsum[w];
            out_scalar[0] = (float)(0.5 * v);
        }
    }
}

extern "C" void kernel_launch(void* const* d_in, const int* in_sizes, int n_in,
                              void* d_out, int out_size) {
    const float* x = (const float*)d_in[0];
    float* out     = (float*)d_out;
    int n  = in_sizes[0];          // 67108864, divisible by 4
    int n4 = n >> 2;

    step_kernel<<<NBLOCKS, NTHREADS>>>((const float4*)x, (float4*)out, n4, out + n);
}